// round 15
// baseline (speedup 1.0000x reference)
#include <cuda_runtime.h>

// Time2Vec: out[b,l,d*64+e] = (e==0) ? x*W[d,0]+b[d,0] : sin(x*W[d,e]+b[d,e])
// x: (32,4096,8) fp32, W/b: (8,64) fp32, out: (32,4096,512) fp32 = 16,777,216 quads.
//
// R13 was an infra failure (container died twice) — re-running the identical
// geometry probe: THREADS=512 x ITER=2 at the proven 16KB tile / 16384 blocks.
// Block-size curve so far: 128t=46.9us, 256t=43.5us (champion), 512t=?
// All other design choices are the bench-proven champion set: STG.128 +
// st.global.wt, loop-invariant (d,e)/w4/b4, front-batched __ldcs x loads.

constexpr int N_QUADS     = 1 << 24;                 // 16,777,216
constexpr int THREADS     = 512;
constexpr int ITER        = 2;
constexpr int BLOCK_QUADS = THREADS * ITER;          // 1024 quads = 16 KB contiguous
constexpr int BLOCKS      = N_QUADS / BLOCK_QUADS;   // 16384
constexpr int XITER       = THREADS / 16;            // 32 x-elements per iter step

__global__ __launch_bounds__(THREADS, 4)
void time2vec_kernel(const float* __restrict__ x,
                     const float* __restrict__ W,
                     const float* __restrict__ B,
                     float4* __restrict__ out)
{
    const int q0 = blockIdx.x * BLOCK_QUADS + threadIdx.x;

    // loop-invariant coordinates (block offset mult of 1024, per-iter stride
    // 512 — both multiples of 128 quads -> (d,e) depend only on tid)
    const int e = (q0 & 15) << 2;        // starting e within [0,64)
    const int d = (q0 >> 4) & 7;         // D = 8
    const bool first = (e == 0);         // passthrough lane

    const float4 w4 = __ldg((const float4*)(W + d * 64 + e));
    const float4 b4 = __ldg((const float4*)(B + d * 64 + e));

    const int x0 = q0 >> 4;

    // front-batch the streaming x loads (each read exactly once)
    float xv[ITER];
    #pragma unroll
    for (int i = 0; i < ITER; i++)
        xv[i] = __ldcs(&x[x0 + i * XITER]);

    #pragma unroll
    for (int i = 0; i < ITER; i++) {
        const float v0 = fmaf(xv[i], w4.x, b4.x);
        float4 r;
        r.x = first ? v0 : __sinf(v0);
        r.y = __sinf(fmaf(xv[i], w4.y, b4.y));
        r.z = __sinf(fmaf(xv[i], w4.z, b4.z));
        r.w = __sinf(fmaf(xv[i], w4.w, b4.w));

        __stwt(&out[q0 + i * THREADS], r);   // dense 16KB per block
    }
}

extern "C" void kernel_launch(void* const* d_in, const int* in_sizes, int n_in,
                              void* d_out, int out_size)
{
    const float* x = (const float*)d_in[0];
    const float* W = (const float*)d_in[1];
    const float* B = (const float*)d_in[2];
    time2vec_kernel<<<BLOCKS, THREADS>>>(x, W, B, (float4*)d_out);
}

// round 16
// speedup vs baseline: 1.1816x; 1.1816x over previous
#include <cuda_runtime.h>

// Time2Vec: out[b,l,d*64+e] = (e==0) ? x*W[d,0]+b[d,0] : sin(x*W[d,e]+b[d,e])
// x: (32,4096,8) fp32, W/b: (8,64) fp32, out: (32,4096,512) fp32 = 16,777,216 quads.
//
// FINAL champion kernel (verified twice: 43.5us / 44.1us, ~5.2 TB/s effective
// write stream = the HBM write-turnaround/LTS floor on sm_103a). Every design
// choice below is the measured optimum of a completed search:
//   - 256 threads x ITER=4 -> 16KB dense tile, 16384 blocks
//     (tile parabola: 32KB=45.2, 16KB=43.5, 8KB=47.8;
//      width parabola: 128t=46.9, 256t=43.5, 512t=53.3)
//   - direct STG.128 + st.global.wt (TMA bulk store +18us, v8 stores +13us,
//     persistent CTAs +16us — all rejected on evidence)
//   - loop-invariant (d,e): all strides are multiples of 128 quads, so the
//     w4/b4 coefficients are per-thread registers; zero shared memory
//   - front-batched __ldcs x loads (each x element read exactly once)
//   - __sinf (MUFU): rel_err 1.77e-07, stable across all runs

constexpr int N_QUADS     = 1 << 24;                 // 16,777,216
constexpr int THREADS     = 256;
constexpr int ITER        = 4;
constexpr int BLOCK_QUADS = THREADS * ITER;          // 1024 quads = 16 KB contiguous
constexpr int BLOCKS      = N_QUADS / BLOCK_QUADS;   // 16384
constexpr int XITER       = THREADS / 16;            // 16 x-elements per iter step

__global__ __launch_bounds__(THREADS, 8)
void time2vec_kernel(const float* __restrict__ x,
                     const float* __restrict__ W,
                     const float* __restrict__ B,
                     float4* __restrict__ out)
{
    const int q0 = blockIdx.x * BLOCK_QUADS + threadIdx.x;

    // loop-invariant coordinates (block offset mult of 1024, per-iter stride
    // 256 — both multiples of 128 quads -> (d,e) depend only on tid)
    const int e = (q0 & 15) << 2;        // starting e within [0,64)
    const int d = (q0 >> 4) & 7;         // D = 8
    const bool first = (e == 0);         // passthrough lane

    const float4 w4 = __ldg((const float4*)(W + d * 64 + e));
    const float4 b4 = __ldg((const float4*)(B + d * 64 + e));

    const int x0 = q0 >> 4;

    // front-batch the streaming x loads (each read exactly once)
    float xv[ITER];
    #pragma unroll
    for (int i = 0; i < ITER; i++)
        xv[i] = __ldcs(&x[x0 + i * XITER]);

    #pragma unroll
    for (int i = 0; i < ITER; i++) {
        const float v0 = fmaf(xv[i], w4.x, b4.x);
        float4 r;
        r.x = first ? v0 : __sinf(v0);
        r.y = __sinf(fmaf(xv[i], w4.y, b4.y));
        r.z = __sinf(fmaf(xv[i], w4.z, b4.z));
        r.w = __sinf(fmaf(xv[i], w4.w, b4.w));

        __stwt(&out[q0 + i * THREADS], r);   // dense 16KB per block
    }
}

extern "C" void kernel_launch(void* const* d_in, const int* in_sizes, int n_in,
                              void* d_out, int out_size)
{
    const float* x = (const float*)d_in[0];
    const float* W = (const float*)d_in[1];
    const float* B = (const float*)d_in[2];
    time2vec_kernel<<<BLOCKS, THREADS>>>(x, W, B, (float4*)d_out);
}

// round 17
// speedup vs baseline: 1.2250x; 1.0368x over previous
#include <cuda_runtime.h>

// Time2Vec: out[b,l,d*64+e] = (e==0) ? x*W[d,0]+b[d,0] : sin(x*W[d,e]+b[d,e])
// x: (32,4096,8) fp32, W/b: (8,64) fp32, out: (32,4096,512) fp32 = 16,777,216 quads.
//
// Champion structure (256t x ITER=4, 16KB dense tiles, 16384 blocks,
// STG.128 + st.global.wt, loop-invariant (d,e)/w4/b4, front-batched __ldcs).
// This round's single change: front-batch the STORES too — compute all four
// r[] quads first, then issue the four __stwt back-to-back so they hit the
// LSU at its 4-cyc structural floor as one contiguous burst, decoupled from
// the sin latency chains. Same instructions, same addresses, same policies.

constexpr int N_QUADS     = 1 << 24;                 // 16,777,216
constexpr int THREADS     = 256;
constexpr int ITER        = 4;
constexpr int BLOCK_QUADS = THREADS * ITER;          // 1024 quads = 16 KB contiguous
constexpr int BLOCKS      = N_QUADS / BLOCK_QUADS;   // 16384
constexpr int XITER       = THREADS / 16;            // 16 x-elements per iter step

__global__ __launch_bounds__(THREADS, 8)
void time2vec_kernel(const float* __restrict__ x,
                     const float* __restrict__ W,
                     const float* __restrict__ B,
                     float4* __restrict__ out)
{
    const int q0 = blockIdx.x * BLOCK_QUADS + threadIdx.x;

    // loop-invariant coordinates (block offset mult of 1024, per-iter stride
    // 256 — both multiples of 128 quads -> (d,e) depend only on tid)
    const int e = (q0 & 15) << 2;        // starting e within [0,64)
    const int d = (q0 >> 4) & 7;         // D = 8
    const bool first = (e == 0);         // passthrough lane

    const float4 w4 = __ldg((const float4*)(W + d * 64 + e));
    const float4 b4 = __ldg((const float4*)(B + d * 64 + e));

    const int x0 = q0 >> 4;

    // front-batch the streaming x loads (each read exactly once)
    float xv[ITER];
    #pragma unroll
    for (int i = 0; i < ITER; i++)
        xv[i] = __ldcs(&x[x0 + i * XITER]);

    // compute all quads first...
    float4 r[ITER];
    #pragma unroll
    for (int i = 0; i < ITER; i++) {
        const float v0 = fmaf(xv[i], w4.x, b4.x);
        r[i].x = first ? v0 : __sinf(v0);
        r[i].y = __sinf(fmaf(xv[i], w4.y, b4.y));
        r[i].z = __sinf(fmaf(xv[i], w4.z, b4.z));
        r[i].w = __sinf(fmaf(xv[i], w4.w, b4.w));
    }

    // ...then drain all stores back-to-back (LSU 4-cyc floor, one burst)
    #pragma unroll
    for (int i = 0; i < ITER; i++)
        __stwt(&out[q0 + i * THREADS], r[i]);
}

extern "C" void kernel_launch(void* const* d_in, const int* in_sizes, int n_in,
                              void* d_out, int out_size)
{
    const float* x = (const float*)d_in[0];
    const float* W = (const float*)d_in[1];
    const float* B = (const float*)d_in[2];
    time2vec_kernel<<<BLOCKS, THREADS>>>(x, W, B, (float4*)d_out);
}